// round 1
// baseline (speedup 1.0000x reference)
#include <cuda_runtime.h>
#include <cstdint>

// Problem constants (fixed shape instance)
constexpr int B = 64;
constexpr int Q = 1024;
constexpr int N = 2048;
constexpr int C = 2048;
constexpr int P = 512;
constexpr int W = 256;     // window
constexpr int HALF = W / 2;

// GEMM tiling for H = c_t @ w_p^T  (B x P), K = C split into KS chunks
constexpr int KC = 64;          // K chunk
constexpr int KS = C / KC;      // 32 splits
constexpr int PT = 32;          // P tile per block
constexpr int NPT = P / PT;     // 16 tiles
constexpr int SSTRIDE = KC + 4; // smem row stride (pad to dodge bank conflicts)

// Scratch (allocation-free rule: __device__ globals)
__device__ float d_Hpart[KS * B * P];   // 4 MB partial sums
__device__ float d_gw[B * W];           // gaussian weights
__device__ int   d_base[B];             // window start index per batch

// ---------------------------------------------------------------------------
// Kernel A: partial GEMM  Hpart[ks][b][j] = sum_{k in chunk ks} c_t[b,k]*w_p[j,k]
// grid: (NPT, KS), block: 256
// ---------------------------------------------------------------------------
__global__ __launch_bounds__(256) void gemm_hpart_kernel(
    const float* __restrict__ c_t, const float* __restrict__ w_p)
{
    __shared__ float sc[B][SSTRIDE];   // c_t chunk: 64 x 64
    __shared__ float sw[PT][SSTRIDE];  // w_p chunk: 32 x 64

    const int pt = blockIdx.x;
    const int ks = blockIdx.y;
    const int k0 = ks * KC;
    const int t  = threadIdx.x;

    // Load c_t chunk: 64 rows x 16 float4 = 1024 float4, 4 per thread
#pragma unroll
    for (int r = 0; r < 4; r++) {
        int i = t + 256 * r;
        int row = i >> 4, c4 = i & 15;
        float4 v = *reinterpret_cast<const float4*>(c_t + (size_t)row * C + k0 + c4 * 4);
        float* dst = &sc[row][c4 * 4];
        dst[0] = v.x; dst[1] = v.y; dst[2] = v.z; dst[3] = v.w;
    }
    // Load w_p chunk: 32 rows x 16 float4 = 512 float4, 2 per thread
#pragma unroll
    for (int r = 0; r < 2; r++) {
        int i = t + 256 * r;
        int row = i >> 4, c4 = i & 15;
        float4 v = *reinterpret_cast<const float4*>(w_p + (size_t)(pt * PT + row) * C + k0 + c4 * 4);
        float* dst = &sw[row][c4 * 4];
        dst[0] = v.x; dst[1] = v.y; dst[2] = v.z; dst[3] = v.w;
    }
    __syncthreads();

    // Each thread: 2 batches x 4 j-columns
    const int tx = t & 7;         // j group
    const int ty = t >> 3;        // 0..31
    const int b0 = ty, b1 = ty + 32;
    const int j0 = tx * 4;

    float acc[2][4] = {};
#pragma unroll
    for (int k = 0; k < KC; k += 4) {
        float4 ca = *reinterpret_cast<const float4*>(&sc[b0][k]);
        float4 cb = *reinterpret_cast<const float4*>(&sc[b1][k]);
#pragma unroll
        for (int jj = 0; jj < 4; jj++) {
            float4 wv = *reinterpret_cast<const float4*>(&sw[j0 + jj][k]);
            acc[0][jj] += ca.x * wv.x + ca.y * wv.y + ca.z * wv.z + ca.w * wv.w;
            acc[1][jj] += cb.x * wv.x + cb.y * wv.y + cb.z * wv.z + cb.w * wv.w;
        }
    }

    const int jg = pt * PT + j0;
#pragma unroll
    for (int jj = 0; jj < 4; jj++) {
        d_Hpart[((size_t)ks * B + b0) * P + jg + jj] = acc[0][jj];
        d_Hpart[((size_t)ks * B + b1) * P + jg + jj] = acc[1][jj];
    }
}

// ---------------------------------------------------------------------------
// Kernel B: reduce K-splits, tanh, dot with v_p, sigmoid -> p_t; emit weights
// grid: B blocks, block: 512 threads (one per P row)
// ---------------------------------------------------------------------------
__global__ __launch_bounds__(512) void head_kernel(const float* __restrict__ v_p)
{
    const int b = blockIdx.x;
    const int j = threadIdx.x;   // 0..511

    float s = 0.f;
#pragma unroll 8
    for (int ks = 0; ks < KS; ks++)
        s += d_Hpart[((size_t)ks * B + b) * P + j];

    float part = v_p[j] * tanhf(s);

    __shared__ float red[512];
    red[j] = part;
    __syncthreads();
#pragma unroll
    for (int o = 256; o > 0; o >>= 1) {
        if (j < o) red[j] += red[j + o];
        __syncthreads();
    }

    __shared__ float s_pt;
    __shared__ int   s_p;
    if (j == 0) {
        float x   = red[0];
        float loc = 1.f / (1.f + expf(-x));
        float pt  = loc * (float)(N + 1 - 2);   // loc * 2047
        int   p   = (int)rintf(pt);             // jnp.round = round-half-even
        s_pt = pt;
        s_p  = p;
        d_base[b] = p - HALF;                   // n start = p - 128
    }
    __syncthreads();

    if (j < W) {
        int n = s_p - HALF + j;                 // = s_i - 1, always in-bounds here
        float d = ((float)n - s_pt) * (1.0f / (float)HALF);
        d_gw[b * W + j] = expf(-2.f * d * d);
    }
}

// ---------------------------------------------------------------------------
// Kernel C: s_t[b,q] = sum_w g[b,w] * q_i[b, q, base + w]
// grid: (Q/8, B), block: 256 (one warp per q row)
// ---------------------------------------------------------------------------
__global__ __launch_bounds__(256) void window_sum_kernel(
    const float* __restrict__ q_i, float* __restrict__ out)
{
    __shared__ float g[W];
    __shared__ int   s_base;

    const int b = blockIdx.y;
    const int t = threadIdx.x;

    if (t < W) g[t] = d_gw[b * W + t];
    if (t == 0) {
        int base = d_base[b];
        // safety clamp (never triggered for this input distribution)
        if (base < 0) base = 0;
        if (base > N - W) base = N - W;
        s_base = base;
    }
    __syncthreads();

    const int warp = t >> 5, lane = t & 31;
    const int q = blockIdx.x * 8 + warp;
    const float* row = q_i + ((size_t)b * Q + q) * N + s_base;

    float acc = 0.f;
    float x[8];
#pragma unroll
    for (int i = 0; i < 8; i++) x[i] = __ldg(row + lane + 32 * i);
#pragma unroll
    for (int i = 0; i < 8; i++) acc += g[lane + 32 * i] * x[i];

#pragma unroll
    for (int o = 16; o > 0; o >>= 1)
        acc += __shfl_down_sync(0xffffffffu, acc, o);

    if (lane == 0) out[(size_t)b * Q + q] = acc;
}

// ---------------------------------------------------------------------------
extern "C" void kernel_launch(void* const* d_in, const int* in_sizes, int n_in,
                              void* d_out, int out_size)
{
    const float* q_i = (const float*)d_in[0];  // (B,Q,N)
    const float* c_t = (const float*)d_in[1];  // (B,C)
    // d_in[2] = w_a : provably cancels out (softmax over singleton axis == 1)
    const float* w_p = (const float*)d_in[3];  // (P,C)
    const float* v_p = (const float*)d_in[4];  // (1,P)
    // d_in[5] = window (constant 256, baked into W)
    float* out = (float*)d_out;                // (B,Q)

    gemm_hpart_kernel<<<dim3(NPT, KS), 256>>>(c_t, w_p);
    head_kernel<<<B, 512>>>(v_p);
    window_sum_kernel<<<dim3(Q / 8, B), 256>>>(q_i, out);
}

// round 2
// speedup vs baseline: 1.5676x; 1.5676x over previous
#include <cuda_runtime.h>
#include <cstdint>

// Problem constants (fixed shape instance)
constexpr int B = 64;
constexpr int Q = 1024;
constexpr int N = 2048;
constexpr int C = 2048;
constexpr int P = 512;
constexpr int W = 256;
constexpr int HALF = W / 2;

// GEMM tiling: block tile = 64b x 256j x 32k, 64 K-splits, grid (2, 64)
constexpr int KC  = 32;
constexpr int KS  = C / KC;   // 64
constexpr int JT  = 256;
constexpr int NJT = P / JT;   // 2
constexpr int SCST = 68;      // sc row stride (floats), 16B-aligned, conflict-free
constexpr int SWST = 260;     // sw row stride

// Scratch (__device__ globals: allocation-free rule)
__device__ float d_Hpart[KS * B * P];   // 8 MB split partials
__device__ float d_gw[B * W];
__device__ int   d_base[B];

__device__ __forceinline__ unsigned long long pk2(float lo, float hi) {
    unsigned long long r;
    asm("mov.b64 %0, {%1, %2};" : "=l"(r) : "f"(lo), "f"(hi));
    return r;
}
__device__ __forceinline__ void fma2(unsigned long long& d,
                                     unsigned long long a, unsigned long long b) {
    asm("fma.rn.f32x2 %0, %1, %2, %0;" : "+l"(d) : "l"(a), "l"(b));
}
__device__ __forceinline__ float2 up2(unsigned long long v) {
    float2 f;
    asm("mov.b64 {%0, %1}, %2;" : "=f"(f.x), "=f"(f.y) : "l"(v));
    return f;
}

// ---------------------------------------------------------------------------
// Kernel A: Hpart[ks][b][j] = sum_{k in chunk} c_t[b,k] * w_p[j,k]
// grid (NJT, KS), 256 threads. Thread tile: 8b x 8j via f32x2 outer product.
// ---------------------------------------------------------------------------
__global__ __launch_bounds__(256) void gemm_kernel(
    const float* __restrict__ c_t, const float* __restrict__ w_p)
{
    __shared__ float sc[KC][SCST];   // k-major c tile: 32 x 64
    __shared__ float sw[KC][SWST];   // k-major w tile: 32 x 256

    const int jt = blockIdx.x;
    const int ks = blockIdx.y;
    const int k0 = ks * KC;
    const int t  = threadIdx.x;
    const int kl  = t & 31;          // k lane (coalesced global reads)
    const int grp = t >> 5;          // 0..7

    // Load c tile (64b x 32k), transposed store as float4-in-b (conflict-free)
#pragma unroll
    for (int it = 0; it < 2; it++) {
        int bq = grp + 8 * it;       // 0..15
        float v0 = __ldg(c_t + (size_t)(bq * 4 + 0) * C + k0 + kl);
        float v1 = __ldg(c_t + (size_t)(bq * 4 + 1) * C + k0 + kl);
        float v2 = __ldg(c_t + (size_t)(bq * 4 + 2) * C + k0 + kl);
        float v3 = __ldg(c_t + (size_t)(bq * 4 + 3) * C + k0 + kl);
        *reinterpret_cast<float4*>(&sc[kl][bq * 4]) = make_float4(v0, v1, v2, v3);
    }
    // Load w tile (256j x 32k), transposed store
#pragma unroll
    for (int it = 0; it < 8; it++) {
        int jq = grp + 8 * it;       // 0..63
        const float* wr = w_p + (size_t)(jt * JT + jq * 4) * C + k0 + kl;
        float v0 = __ldg(wr);
        float v1 = __ldg(wr + C);
        float v2 = __ldg(wr + 2 * C);
        float v3 = __ldg(wr + 3 * C);
        *reinterpret_cast<float4*>(&sw[kl][jq * 4]) = make_float4(v0, v1, v2, v3);
    }
    __syncthreads();

    // Compute mapping: warp lanes share bg (c reads broadcast), jg varies.
    const int jg = t & 31;
    const int bg = t >> 5;
    const int b0 = bg * 8;
    const int j0 = jg * 4;           // thread's j quads: j0 and 128+j0

    unsigned long long acc[8][4];    // [jj][b-pair], f32x2 = (b_even, b_odd)
#pragma unroll
    for (int jj = 0; jj < 8; jj++)
#pragma unroll
        for (int bp = 0; bp < 4; bp++) acc[jj][bp] = 0ull;

#pragma unroll 8
    for (int k = 0; k < KC; k++) {
        float4 ca = *reinterpret_cast<const float4*>(&sc[k][b0]);
        float4 cb = *reinterpret_cast<const float4*>(&sc[k][b0 + 4]);
        float4 wa = *reinterpret_cast<const float4*>(&sw[k][j0]);
        float4 wb = *reinterpret_cast<const float4*>(&sw[k][128 + j0]);

        unsigned long long cp[4] = {
            pk2(ca.x, ca.y), pk2(ca.z, ca.w),
            pk2(cb.x, cb.y), pk2(cb.z, cb.w)
        };
        float wv[8] = {wa.x, wa.y, wa.z, wa.w, wb.x, wb.y, wb.z, wb.w};
#pragma unroll
        for (int jj = 0; jj < 8; jj++) {
            unsigned long long wp2 = pk2(wv[jj], wv[jj]);
#pragma unroll
            for (int bp = 0; bp < 4; bp++) fma2(acc[jj][bp], wp2, cp[bp]);
        }
    }

    // Epilogue: coalesced float4 stores
#pragma unroll
    for (int bp = 0; bp < 4; bp++) {
        float2 v[8];
#pragma unroll
        for (int jj = 0; jj < 8; jj++) v[jj] = up2(acc[jj][bp]);
        int bE = b0 + bp * 2;
        size_t rE = ((size_t)ks * B + bE) * P + jt * JT;
        size_t rO = rE + P;          // bE+1
        *reinterpret_cast<float4*>(&d_Hpart[rE + j0])       = make_float4(v[0].x, v[1].x, v[2].x, v[3].x);
        *reinterpret_cast<float4*>(&d_Hpart[rE + 128 + j0]) = make_float4(v[4].x, v[5].x, v[6].x, v[7].x);
        *reinterpret_cast<float4*>(&d_Hpart[rO + j0])       = make_float4(v[0].y, v[1].y, v[2].y, v[3].y);
        *reinterpret_cast<float4*>(&d_Hpart[rO + 128 + j0]) = make_float4(v[4].y, v[5].y, v[6].y, v[7].y);
    }
}

// ---------------------------------------------------------------------------
// Kernel B: reduce K-splits (float4), tanh, dot v_p, sigmoid -> p_t, weights
// grid: B blocks, 512 threads
// ---------------------------------------------------------------------------
__global__ __launch_bounds__(512) void head_kernel(const float* __restrict__ v_p)
{
    const int b = blockIdx.x;
    const int t = threadIdx.x;
    const int jq = t & 127;          // j quad 0..127
    const int g  = t >> 7;           // split group 0..3

    float4 s = make_float4(0.f, 0.f, 0.f, 0.f);
#pragma unroll 4
    for (int ks = g; ks < KS; ks += 4) {
        float4 h = *reinterpret_cast<const float4*>(
            &d_Hpart[((size_t)ks * B + b) * P + jq * 4]);
        s.x += h.x; s.y += h.y; s.z += h.z; s.w += h.w;
    }
    __shared__ float4 hs[4][128];
    hs[g][jq] = s;
    __syncthreads();

    __shared__ float warp_part[4];
    if (t < 128) {
        float4 a = hs[0][t], b4 = hs[1][t], c4 = hs[2][t], e4 = hs[3][t];
        float h0 = ((a.x + b4.x) + c4.x) + e4.x;
        float h1 = ((a.y + b4.y) + c4.y) + e4.y;
        float h2 = ((a.z + b4.z) + c4.z) + e4.z;
        float h3 = ((a.w + b4.w) + c4.w) + e4.w;
        float part = v_p[t * 4 + 0] * tanhf(h0)
                   + v_p[t * 4 + 1] * tanhf(h1)
                   + v_p[t * 4 + 2] * tanhf(h2)
                   + v_p[t * 4 + 3] * tanhf(h3);
#pragma unroll
        for (int o = 16; o > 0; o >>= 1)
            part += __shfl_down_sync(0xffffffffu, part, o);
        if ((t & 31) == 0) warp_part[t >> 5] = part;
    }
    __syncthreads();

    __shared__ float s_pt;
    __shared__ int   s_p;
    if (t == 0) {
        float x   = ((warp_part[0] + warp_part[1]) + warp_part[2]) + warp_part[3];
        float loc = 1.f / (1.f + expf(-x));
        float pt  = loc * (float)(N - 1);       // loc * 2047
        int   p   = (int)rintf(pt);             // round-half-even like jnp.round
        s_pt = pt;
        s_p  = p;
        int base = p - HALF;
        if (base < 0) base = 0;
        if (base > N - W) base = N - W;
        d_base[b] = base;
    }
    __syncthreads();

    if (t < W) {
        int n = s_p - HALF + t;
        float d = ((float)n - s_pt) * (1.0f / (float)HALF);
        d_gw[b * W + t] = expf(-2.f * d * d);
    }
}

// ---------------------------------------------------------------------------
// Kernel C: s_t[b,q] = sum_w g[b,w] * q_i[b, q, base + w]
// grid (Q/8, B), 256 threads (one warp per q row)
// ---------------------------------------------------------------------------
__global__ __launch_bounds__(256) void window_sum_kernel(
    const float* __restrict__ q_i, float* __restrict__ out)
{
    __shared__ float g[W];
    __shared__ int   s_base;

    const int b = blockIdx.y;
    const int t = threadIdx.x;

    g[t] = d_gw[b * W + t];          // blockDim == W == 256
    if (t == 0) s_base = d_base[b];
    __syncthreads();

    const int warp = t >> 5, lane = t & 31;
    const int q = blockIdx.x * 8 + warp;
    const float* row = q_i + ((size_t)b * Q + q) * N + s_base;

    float x[8];
#pragma unroll
    for (int i = 0; i < 8; i++) x[i] = __ldg(row + lane + 32 * i);
    float acc = 0.f;
#pragma unroll
    for (int i = 0; i < 8; i++) acc += g[lane + 32 * i] * x[i];

#pragma unroll
    for (int o = 16; o > 0; o >>= 1)
        acc += __shfl_down_sync(0xffffffffu, acc, o);

    if (lane == 0) out[(size_t)b * Q + q] = acc;
}

// ---------------------------------------------------------------------------
extern "C" void kernel_launch(void* const* d_in, const int* in_sizes, int n_in,
                              void* d_out, int out_size)
{
    const float* q_i = (const float*)d_in[0];  // (B,Q,N)
    const float* c_t = (const float*)d_in[1];  // (B,C)
    // d_in[2] = w_a : cancels (softmax over singleton axis == 1)
    const float* w_p = (const float*)d_in[3];  // (P,C)
    const float* v_p = (const float*)d_in[4];  // (1,P)
    float* out = (float*)d_out;                // (B,Q)

    gemm_kernel<<<dim3(NJT, KS), 256>>>(c_t, w_p);
    head_kernel<<<B, 512>>>(v_p);
    window_sum_kernel<<<dim3(Q / 8, B), 256>>>(q_i, out);
}

// round 3
// speedup vs baseline: 1.6316x; 1.0408x over previous
#include <cuda_runtime.h>
#include <cstdint>

// Problem constants (fixed shape instance)
constexpr int B = 64;
constexpr int Q = 1024;
constexpr int N = 2048;
constexpr int C = 2048;
constexpr int P = 512;
constexpr int W = 256;
constexpr int HALF = W / 2;

// GEMM tiling: block tile = 64b x 64j x 64k, grid (8 j-tiles, 32 k-splits)
constexpr int KC  = 64;
constexpr int KS  = C / KC;   // 32
constexpr int JT  = 64;
constexpr int NJT = P / JT;   // 8
constexpr int SST = 68;       // smem row stride (floats): conflict-free, 16B-aligned

// Scratch (__device__ globals: allocation-free rule)
__device__ float d_Hpart[KS * B * P];   // 4 MB split partials
__device__ float d_gw[B * W];
__device__ int   d_base[B];

__device__ __forceinline__ unsigned long long pk2(float lo, float hi) {
    unsigned long long r;
    asm("mov.b64 %0, {%1, %2};" : "=l"(r) : "f"(lo), "f"(hi));
    return r;
}
__device__ __forceinline__ void fma2(unsigned long long& d,
                                     unsigned long long a, unsigned long long b) {
    asm("fma.rn.f32x2 %0, %1, %2, %0;" : "+l"(d) : "l"(a), "l"(b));
}

// ---------------------------------------------------------------------------
// Kernel A: Hpart[ks][b][j] = sum_{k in chunk ks} c_t[b,k] * w_p[j,k]
// grid (NJT, KS), 256 threads. Thread tile 4b x 4j, f32x2 over j-pairs.
// ---------------------------------------------------------------------------
__global__ __launch_bounds__(256, 4) void gemm_kernel(
    const float* __restrict__ c_t, const float* __restrict__ w_p)
{
    __shared__ float sc[KC][SST];   // k-major c tile: 64k x 64b
    __shared__ float sw[KC][SST];   // k-major w tile: 64k x 64j

    const int jt = blockIdx.x;
    const int ks = blockIdx.y;
    const int k0 = ks * KC;
    const int t  = threadIdx.x;
    const int kl  = t & 63;          // k lane (coalesced global reads)
    const int grp = t >> 6;          // 0..3

    // c tile: 16 b-quads, 4 per group. 4 scalar LDG -> 1 STS.128 (transposed)
#pragma unroll
    for (int it = 0; it < 4; it++) {
        int bq = grp * 4 + it;       // 0..15
        const float* cr = c_t + (size_t)(bq * 4) * C + k0 + kl;
        float v0 = __ldg(cr);
        float v1 = __ldg(cr + C);
        float v2 = __ldg(cr + 2 * C);
        float v3 = __ldg(cr + 3 * C);
        *reinterpret_cast<float4*>(&sc[kl][bq * 4]) = make_float4(v0, v1, v2, v3);
    }
    // w tile: 16 j-quads
#pragma unroll
    for (int it = 0; it < 4; it++) {
        int jq = grp * 4 + it;       // 0..15
        const float* wr = w_p + (size_t)(jt * JT + jq * 4) * C + k0 + kl;
        float v0 = __ldg(wr);
        float v1 = __ldg(wr + C);
        float v2 = __ldg(wr + 2 * C);
        float v3 = __ldg(wr + 3 * C);
        *reinterpret_cast<float4*>(&sw[kl][jq * 4]) = make_float4(v0, v1, v2, v3);
    }
    __syncthreads();

    // Compute mapping: half-warp shares b (c reads broadcast), j varies.
    const int jg = t & 15;
    const int bg = t >> 4;
    const int b0 = bg * 4;
    const int j0 = jg * 4;

    unsigned long long acc[4][2];    // [bb][j-pair]: f32x2 = (j even, j odd)
#pragma unroll
    for (int bb = 0; bb < 4; bb++) { acc[bb][0] = 0ull; acc[bb][1] = 0ull; }

#pragma unroll 8
    for (int k = 0; k < KC; k++) {
        float4 ca = *reinterpret_cast<const float4*>(&sc[k][b0]);
        ulonglong2 wv = *reinterpret_cast<const ulonglong2*>(&sw[k][j0]);
        unsigned long long cd0 = pk2(ca.x, ca.x);
        unsigned long long cd1 = pk2(ca.y, ca.y);
        unsigned long long cd2 = pk2(ca.z, ca.z);
        unsigned long long cd3 = pk2(ca.w, ca.w);
        fma2(acc[0][0], cd0, wv.x); fma2(acc[0][1], cd0, wv.y);
        fma2(acc[1][0], cd1, wv.x); fma2(acc[1][1], cd1, wv.y);
        fma2(acc[2][0], cd2, wv.x); fma2(acc[2][1], cd2, wv.y);
        fma2(acc[3][0], cd3, wv.x); fma2(acc[3][1], cd3, wv.y);
    }

    // Epilogue: acc rows are already j-contiguous pairs -> direct STG.128
#pragma unroll
    for (int bb = 0; bb < 4; bb++) {
        size_t row = ((size_t)ks * B + (b0 + bb)) * P + jt * JT + j0;
        *reinterpret_cast<ulonglong2*>(&d_Hpart[row]) =
            make_ulonglong2(acc[bb][0], acc[bb][1]);
    }
}

// ---------------------------------------------------------------------------
// Kernel B: reduce K-splits (float4), tanh, dot v_p, sigmoid -> p_t, weights
// grid: B blocks, 512 threads
// ---------------------------------------------------------------------------
__global__ __launch_bounds__(512) void head_kernel(const float* __restrict__ v_p)
{
    const int b = blockIdx.x;
    const int t = threadIdx.x;
    const int jq = t & 127;          // j quad 0..127
    const int g  = t >> 7;           // split group 0..3

    float4 s = make_float4(0.f, 0.f, 0.f, 0.f);
#pragma unroll
    for (int ks = g; ks < KS; ks += 4) {
        float4 h = *reinterpret_cast<const float4*>(
            &d_Hpart[((size_t)ks * B + b) * P + jq * 4]);
        s.x += h.x; s.y += h.y; s.z += h.z; s.w += h.w;
    }
    __shared__ float4 hs[4][128];
    hs[g][jq] = s;
    __syncthreads();

    __shared__ float warp_part[4];
    if (t < 128) {
        float4 a = hs[0][t], b4 = hs[1][t], c4 = hs[2][t], e4 = hs[3][t];
        float h0 = ((a.x + b4.x) + c4.x) + e4.x;
        float h1 = ((a.y + b4.y) + c4.y) + e4.y;
        float h2 = ((a.z + b4.z) + c4.z) + e4.z;
        float h3 = ((a.w + b4.w) + c4.w) + e4.w;
        float part = v_p[t * 4 + 0] * tanhf(h0)
                   + v_p[t * 4 + 1] * tanhf(h1)
                   + v_p[t * 4 + 2] * tanhf(h2)
                   + v_p[t * 4 + 3] * tanhf(h3);
#pragma unroll
        for (int o = 16; o > 0; o >>= 1)
            part += __shfl_down_sync(0xffffffffu, part, o);
        if ((t & 31) == 0) warp_part[t >> 5] = part;
    }
    __syncthreads();

    __shared__ float s_pt;
    __shared__ int   s_p;
    if (t == 0) {
        float x   = ((warp_part[0] + warp_part[1]) + warp_part[2]) + warp_part[3];
        float loc = 1.f / (1.f + expf(-x));
        float pt  = loc * (float)(N - 1);       // loc * 2047
        int   p   = (int)rintf(pt);             // round-half-even like jnp.round
        s_pt = pt;
        s_p  = p;
        int base = p - HALF;
        if (base < 0) base = 0;
        if (base > N - W) base = N - W;
        d_base[b] = base;
    }
    __syncthreads();

    if (t < W) {
        int n = s_p - HALF + t;
        float d = ((float)n - s_pt) * (1.0f / (float)HALF);
        d_gw[b * W + t] = expf(-2.f * d * d);
    }
}

// ---------------------------------------------------------------------------
// Kernel C: s_t[b,q] = sum_w g[b,w] * q_i[b, q, base + w]
// grid (Q/8, B), 256 threads (one warp per q row)
// ---------------------------------------------------------------------------
__global__ __launch_bounds__(256) void window_sum_kernel(
    const float* __restrict__ q_i, float* __restrict__ out)
{
    __shared__ float g[W];
    __shared__ int   s_base;

    const int b = blockIdx.y;
    const int t = threadIdx.x;

    g[t] = d_gw[b * W + t];          // blockDim == W == 256
    if (t == 0) s_base = d_base[b];
    __syncthreads();

    const int warp = t >> 5, lane = t & 31;
    const int q = blockIdx.x * 8 + warp;
    const float* row = q_i + ((size_t)b * Q + q) * N + s_base;

    float x[8];
#pragma unroll
    for (int i = 0; i < 8; i++) x[i] = __ldg(row + lane + 32 * i);
    float acc = 0.f;
#pragma unroll
    for (int i = 0; i < 8; i++) acc += g[lane + 32 * i] * x[i];

#pragma unroll
    for (int o = 16; o > 0; o >>= 1)
        acc += __shfl_down_sync(0xffffffffu, acc, o);

    if (lane == 0) out[(size_t)b * Q + q] = acc;
}

// ---------------------------------------------------------------------------
extern "C" void kernel_launch(void* const* d_in, const int* in_sizes, int n_in,
                              void* d_out, int out_size)
{
    const float* q_i = (const float*)d_in[0];  // (B,Q,N)
    const float* c_t = (const float*)d_in[1];  // (B,C)
    // d_in[2] = w_a : cancels (softmax over singleton axis == 1)
    const float* w_p = (const float*)d_in[3];  // (P,C)
    const float* v_p = (const float*)d_in[4];  // (1,P)
    float* out = (float*)d_out;                // (B,Q)

    gemm_kernel<<<dim3(NJT, KS), 256>>>(c_t, w_p);
    head_kernel<<<B, 512>>>(v_p);
    window_sum_kernel<<<dim3(Q / 8, B), 256>>>(q_i, out);
}